// round 3
// baseline (speedup 1.0000x reference)
#include <cuda_runtime.h>
#include <math.h>
#include <float.h>

#define NMAX 50000
#define EMAX 400000
#define RMAX 20000

// Scratch (allocation-free rule: __device__ globals)
__device__ float g_h[NMAX * 128];
__device__ float g_u[NMAX * 128];
__device__ float g_v[NMAX * 128];
__device__ float g_rh[RMAX * 128];
__device__ float g_th[RMAX * 128];
__device__ float g_s[EMAX];
__device__ float g_aggr[NMAX * 128];
__device__ unsigned int g_maxkey;
__device__ float g_sum;

// --- monotonic float<->uint key for atomicMax over signed floats ---
__device__ __forceinline__ unsigned fkey(float f) {
    unsigned b = __float_as_uint(f);
    return (b & 0x80000000u) ? ~b : (b | 0x80000000u);
}
__device__ __forceinline__ float fdecode(unsigned k) {
    return __uint_as_float((k & 0x80000000u) ? (k ^ 0x80000000u) : ~k);
}

// --- packed f32x2 helpers (Blackwell FFMA2 path, PTX-only) ---
__device__ __forceinline__ unsigned long long pack2(float lo, float hi) {
    unsigned long long r;
    asm("mov.b64 %0, {%1, %2};" : "=l"(r) : "f"(lo), "f"(hi));
    return r;
}
__device__ __forceinline__ void ffma2(unsigned long long& d, unsigned long long a,
                                      unsigned long long b) {
    asm("fma.rn.f32x2 %0, %1, %2, %0;" : "+l"(d) : "l"(a), "l"(b));
}
__device__ __forceinline__ float2 unpack2(unsigned long long v) {
    float2 r;
    asm("mov.b64 {%0, %1}, %2;" : "=f"(r.x), "=f"(r.y) : "l"(v));
    return r;
}

// ---------------------------------------------------------------------------
// init: zero aggregation buffer, reset softmax scalars
// ---------------------------------------------------------------------------
__global__ void init_k(float* __restrict__ aggr, int n128) {
    int i = blockIdx.x * blockDim.x + threadIdx.x;
    if (i == 0) { g_maxkey = 0u; g_sum = 0.f; }
    for (; i < n128; i += gridDim.x * blockDim.x) aggr[i] = 0.f;
}

// ---------------------------------------------------------------------------
// GEMM: Y[n,128] = (X[n,K] @ W[K,128]) * scale + bias.  K in {64,128}.
// Block = 128 threads (thread t owns output column t), 32 rows per iteration.
// Inner loop uses packed fma.rn.f32x2 (FFMA2): accumulator packs k-parity,
// reduced at the end. scale = 1/(*sumptr) when sumptr != nullptr.
// ---------------------------------------------------------------------------
__global__ void __launch_bounds__(128)
gemm_k(const float* __restrict__ X, const float* __restrict__ W,
       const float* __restrict__ bias, float* __restrict__ Y,
       int n, int K, const float* __restrict__ sumptr) {
    extern __shared__ float sm[];
    float* Ws = sm;           // K*128
    float* Xs = sm + K * 128; // 32*K
    int t = threadIdx.x;
    for (int i = t; i < K * 128; i += 128) Ws[i] = W[i];
    float bv = bias ? bias[t] : 0.f;

    for (int row0 = blockIdx.x * 32; row0 < n; row0 += gridDim.x * 32) {
        int nr = min(32, n - row0);
        __syncthreads();  // protect Xs from previous iteration readers (also covers Ws 1st time)
        for (int i = t; i < nr * K; i += 128) Xs[i] = X[(size_t)row0 * K + i];
        __syncthreads();

        unsigned long long acc[32];
#pragma unroll
        for (int r = 0; r < 32; r++) acc[r] = 0ull;

#pragma unroll 2
        for (int k = 0; k < K; k += 4) {
            unsigned long long wp0 = pack2(Ws[(k + 0) * 128 + t], Ws[(k + 1) * 128 + t]);
            unsigned long long wp1 = pack2(Ws[(k + 2) * 128 + t], Ws[(k + 3) * 128 + t]);
#pragma unroll
            for (int r = 0; r < 32; r++) {
                ulonglong2 xv = *(const ulonglong2*)&Xs[r * K + k];
                ffma2(acc[r], xv.x, wp0);
                ffma2(acc[r], xv.y, wp1);
            }
        }

        float scale = sumptr ? (1.f / *sumptr) : 1.f;
        for (int r = 0; r < nr; r++) {
            float2 p = unpack2(acc[r]);
            Y[(size_t)(row0 + r) * 128 + t] = (p.x + p.y) * scale + bv;
        }
    }
}

// ---------------------------------------------------------------------------
// Edge attention score + fused block max. One warp per edge.
// s[e] = b2 + sum_t W2[t] * relu(u[dst][t] + v[src][t] + dist . Wd[:,t] + b1[t])
// ---------------------------------------------------------------------------
__global__ void edge_k(const int* __restrict__ src, const int* __restrict__ dst,
                       const float* __restrict__ pos,
                       const float* __restrict__ Wd, const float* __restrict__ b1,
                       const float* __restrict__ W2, const float* __restrict__ b2,
                       int E) {
    int gw = (blockIdx.x * blockDim.x + threadIdx.x) >> 5;
    int lane = threadIdx.x & 31;
    int wid = threadIdx.x >> 5;

    float score = -FLT_MAX;
    if (gw < E) {
        int sn = src[gw], dn = dst[gw];
        float dx = pos[dn * 3 + 0] - pos[sn * 3 + 0];
        float dy = pos[dn * 3 + 1] - pos[sn * 3 + 1];
        float dz = pos[dn * 3 + 2] - pos[sn * 3 + 2];

        float4 a  = ((const float4*)(g_u + (size_t)dn * 128))[lane];
        float4 bj = ((const float4*)(g_v + (size_t)sn * 128))[lane];
        float4 c0 = ((const float4*)Wd)[lane];
        float4 c1 = ((const float4*)(Wd + 128))[lane];
        float4 c2 = ((const float4*)(Wd + 256))[lane];
        float4 bb = ((const float4*)b1)[lane];
        float4 w2 = ((const float4*)W2)[lane];

        float v0 = fmaxf(a.x + bj.x + bb.x + dx * c0.x + dy * c1.x + dz * c2.x, 0.f);
        float v1 = fmaxf(a.y + bj.y + bb.y + dx * c0.y + dy * c1.y + dz * c2.y, 0.f);
        float v2 = fmaxf(a.z + bj.z + bb.z + dx * c0.z + dy * c1.z + dz * c2.z, 0.f);
        float v3 = fmaxf(a.w + bj.w + bb.w + dx * c0.w + dy * c1.w + dz * c2.w, 0.f);
        float p = v0 * w2.x + v1 * w2.y + v2 * w2.z + v3 * w2.w;

        for (int o = 16; o; o >>= 1) p += __shfl_xor_sync(0xffffffffu, p, o);
        score = p + b2[0];
        if (lane == 0) g_s[gw] = score;
    }

    __shared__ float wm[8];
    if (lane == 0) wm[wid] = score;
    __syncthreads();
    if (threadIdx.x == 0) {
        float m = wm[0];
        for (int i = 1; i < 8; i++) m = fmaxf(m, wm[i]);
        atomicMax(&g_maxkey, fkey(m));
    }
}

// ---------------------------------------------------------------------------
// Fused exp + global-sum + scatter-add. One warp per edge.
// p = exp(s - max);  aggr[dst] += h[src] * p  (UNNORMALIZED; 1/sum applied in
// the update GEMM epilogue);  g_sum += p.
// Uses red.global.add.v4.f32 (sm_90+) to quarter the REDG op count.
// ---------------------------------------------------------------------------
__global__ void scatter_k(const int* __restrict__ src, const int* __restrict__ dst, int E) {
    int gw = (blockIdx.x * blockDim.x + threadIdx.x) >> 5;
    int lane = threadIdx.x & 31;
    int wid = threadIdx.x >> 5;

    float mx = fdecode(g_maxkey);
    float p = 0.f;
    if (gw < E) {
        p = expf(g_s[gw] - mx);
        int sn = src[gw], dn = dst[gw];
        float4 x = ((const float4*)(g_h + (size_t)sn * 128))[lane];
        float* basep = g_aggr + (size_t)dn * 128 + lane * 4;
        asm volatile("red.global.add.v4.f32 [%0], {%1, %2, %3, %4};"
                     :: "l"(basep), "f"(x.x * p), "f"(x.y * p), "f"(x.z * p), "f"(x.w * p)
                     : "memory");
    }

    __shared__ float ws[8];
    if (lane == 0) ws[wid] = p;
    __syncthreads();
    if (threadIdx.x == 0) {
        float tot = ws[0];
        for (int i = 1; i < 8; i++) tot += ws[i];
        atomicAdd(&g_sum, tot);
    }
}

// ---------------------------------------------------------------------------
// Head: out[row] = relu(R[row] @ W1 + b1) @ W2 + b2 (scalar). One warp/row.
// ---------------------------------------------------------------------------
__global__ void head_k(const float* __restrict__ R, const float* __restrict__ W1,
                       const float* __restrict__ b1, const float* __restrict__ W2,
                       const float* __restrict__ b2, float* __restrict__ out, int n) {
    __shared__ float W1s[128 * 64];
    __shared__ float b1s[64];
    __shared__ float W2s[64];
    __shared__ float rows[8][128];
    int t = threadIdx.x, lane = t & 31, wid = t >> 5;
    for (int i = t; i < 128 * 64; i += 256) W1s[i] = W1[i];
    if (t < 64) { b1s[t] = b1[t]; W2s[t] = W2[t]; }
    __syncthreads();
    float b2v = b2[0];
    for (int row = blockIdx.x * 8 + wid; row < n; row += gridDim.x * 8) {
        ((float4*)rows[wid])[lane] = ((const float4*)(R + (size_t)row * 128))[lane];
        __syncwarp();
        float h0 = b1s[lane], h1 = b1s[lane + 32];
#pragma unroll 8
        for (int k = 0; k < 128; k++) {
            float x = rows[wid][k];
            h0 += x * W1s[k * 64 + lane];
            h1 += x * W1s[k * 64 + lane + 32];
        }
        float p = fmaxf(h0, 0.f) * W2s[lane] + fmaxf(h1, 0.f) * W2s[lane + 32];
        for (int o = 16; o; o >>= 1) p += __shfl_xor_sync(0xffffffffu, p, o);
        if (lane == 0) out[row] = p + b2v;
        __syncwarp();
    }
}

// ---------------------------------------------------------------------------
extern "C" void kernel_launch(void* const* d_in, const int* in_sizes, int n_in,
                              void* d_out, int out_size) {
    const float* mol_x  = (const float*)d_in[0];
    const float* pos    = (const float*)d_in[1];
    const float* rx     = (const float*)d_in[2];
    const float* tx     = (const float*)d_in[3];
    const int*   ei     = (const int*)d_in[4];
    const float* W_node = (const float*)d_in[5];
    const float* b_node = (const float*)d_in[6];
    const float* W_att1 = (const float*)d_in[7];
    const float* b_att1 = (const float*)d_in[8];
    const float* W_att2 = (const float*)d_in[9];
    const float* b_att2 = (const float*)d_in[10];
    const float* W_upd  = (const float*)d_in[11];
    const float* b_upd  = (const float*)d_in[12];
    const float* Wy1 = (const float*)d_in[13];
    const float* by1 = (const float*)d_in[14];
    const float* Wy2 = (const float*)d_in[15];
    const float* by2 = (const float*)d_in[16];
    const float* Wa1 = (const float*)d_in[17];
    const float* ba1 = (const float*)d_in[18];
    const float* Wa2 = (const float*)d_in[19];
    const float* ba2 = (const float*)d_in[20];

    int N  = in_sizes[0] / 64;
    int NR = in_sizes[2] / 64;
    int NT = in_sizes[3] / 64;
    int E  = in_sizes[4] / 2;
    const int* srcP = ei;
    const int* dstP = ei + E;

    float* out   = (float*)d_out;
    float* out_y = out;             // pred_yield  [NR]
    float* out_a = out + NR;        // pred_activity [NT]
    float* out_m = out + NR + NT;   // mol_feats [N,128]

    float *hP, *uP, *vP, *rhP, *thP, *agP, *sumP;
    cudaGetSymbolAddress((void**)&hP,  g_h);
    cudaGetSymbolAddress((void**)&uP,  g_u);
    cudaGetSymbolAddress((void**)&vP,  g_v);
    cudaGetSymbolAddress((void**)&rhP, g_rh);
    cudaGetSymbolAddress((void**)&thP, g_th);
    cudaGetSymbolAddress((void**)&agP, g_aggr);
    cudaGetSymbolAddress((void**)&sumP, g_sum);

    int smem64  = (64 * 128 + 32 * 64) * 4;
    int smem128 = (128 * 128 + 32 * 128) * 4;
    cudaFuncSetAttribute(gemm_k, cudaFuncAttributeMaxDynamicSharedMemorySize, smem128);

    init_k<<<512, 256>>>(agP, N * 128);

    // node encoders
    gemm_k<<<(N  + 31) / 32, 128, smem64>>>(mol_x, W_node, b_node, hP,  N,  64, nullptr);
    gemm_k<<<(NR + 31) / 32, 128, smem64>>>(rx,    W_node, b_node, rhP, NR, 64, nullptr);
    gemm_k<<<(NT + 31) / 32, 128, smem64>>>(tx,    W_node, b_node, thP, NT, 64, nullptr);

    // per-node attention projections: u = h@W_att1[0:128], v = h@W_att1[128:256]
    gemm_k<<<(N + 31) / 32, 128, smem128>>>(hP, W_att1,             nullptr, uP, N, 128, nullptr);
    gemm_k<<<(N + 31) / 32, 128, smem128>>>(hP, W_att1 + 128 * 128, nullptr, vP, N, 128, nullptr);

    // per-edge score + fused global max
    edge_k<<<(E + 7) / 8, 256>>>(srcP, dstP, pos, W_att1 + 256 * 128, b_att1, W_att2, b_att2, E);

    // fused exp + sum + unnormalized scatter-add
    scatter_k<<<(E + 7) / 8, 256>>>(srcP, dstP, E);

    // update GEMM -> mol_feats, with 1/sum folded into the epilogue
    gemm_k<<<(N + 31) / 32, 128, smem128>>>(agP, W_upd, b_upd, out_m, N, 128, sumP);

    // heads
    head_k<<<(NR + 7) / 8, 256>>>(rhP, Wy1, by1, Wy2, by2, out_y, NR);
    head_k<<<(NT + 7) / 8, 256>>>(thP, Wa1, ba1, Wa2, ba2, out_a, NT);
}

// round 4
// speedup vs baseline: 1.5405x; 1.5405x over previous
#include <cuda_runtime.h>
#include <math.h>
#include <float.h>

#define NMAX 50000
#define EMAX 400000
#define RMAX 20000

// Scratch (allocation-free rule: __device__ globals)
__device__ float g_h[NMAX * 128];
__device__ float g_u[NMAX * 128];
__device__ float g_v[NMAX * 128];
__device__ float g_rh[RMAX * 128];
__device__ float g_th[RMAX * 128];
__device__ float g_s[EMAX];
__device__ float g_aggr[NMAX * 128];
__device__ unsigned int g_maxkey;
__device__ float g_sum;

// --- monotonic float<->uint key for atomicMax over signed floats ---
__device__ __forceinline__ unsigned fkey(float f) {
    unsigned b = __float_as_uint(f);
    return (b & 0x80000000u) ? ~b : (b | 0x80000000u);
}
__device__ __forceinline__ float fdecode(unsigned k) {
    return __uint_as_float((k & 0x80000000u) ? (k ^ 0x80000000u) : ~k);
}

// ---------------------------------------------------------------------------
// init: zero aggregation buffer, reset softmax scalars
// ---------------------------------------------------------------------------
__global__ void init_k(float* __restrict__ aggr, int n128) {
    int i = blockIdx.x * blockDim.x + threadIdx.x;
    if (i == 0) { g_maxkey = 0u; g_sum = 0.f; }
    for (; i < n128; i += gridDim.x * blockDim.x) aggr[i] = 0.f;
}

// ---------------------------------------------------------------------------
// GEMM: Y[n,128] = (X[n,K] @ W[K,128]) * scale + bias.  K in {64,128}.
// Block = 128 threads (thread t owns output column t), 32 rows per iteration.
// PERSISTENT grid: W staged in smem ONCE per block, amortized over the
// grid-stride row loop. scale = 1/(*sumptr) when sumptr != nullptr.
// ---------------------------------------------------------------------------
__global__ void __launch_bounds__(128)
gemm_k(const float* __restrict__ X, const float* __restrict__ W,
       const float* __restrict__ bias, float* __restrict__ Y,
       int n, int K, const float* __restrict__ sumptr) {
    extern __shared__ float sm[];
    float* Ws = sm;           // K*128
    float* Xs = sm + K * 128; // 32*K
    int t = threadIdx.x;
    // stage W as float4 (K*128 is a multiple of 512)
    for (int i = t; i < K * 32; i += 128)
        ((float4*)Ws)[i] = ((const float4*)W)[i];
    float bv = bias ? bias[t] : 0.f;

    for (int row0 = blockIdx.x * 32; row0 < n; row0 += gridDim.x * 32) {
        int nr = min(32, n - row0);
        __syncthreads();  // protect Xs from previous iteration readers (covers Ws 1st time)
        for (int i = t; i < nr * (K / 4); i += 128)
            ((float4*)Xs)[i] = ((const float4*)(X + (size_t)row0 * K))[i];
        __syncthreads();

        float acc[32];
#pragma unroll
        for (int r = 0; r < 32; r++) acc[r] = 0.f;

        for (int k4 = 0; k4 < K; k4 += 4) {
            float w0 = Ws[(k4 + 0) * 128 + t];
            float w1 = Ws[(k4 + 1) * 128 + t];
            float w2 = Ws[(k4 + 2) * 128 + t];
            float w3 = Ws[(k4 + 3) * 128 + t];
#pragma unroll
            for (int r = 0; r < 32; r++) {
                float4 xv = *(const float4*)&Xs[r * K + k4];
                acc[r] += xv.x * w0 + xv.y * w1 + xv.z * w2 + xv.w * w3;
            }
        }

        float scale = sumptr ? (1.f / *sumptr) : 1.f;
        for (int r = 0; r < nr; r++)
            Y[(size_t)(row0 + r) * 128 + t] = acc[r] * scale + bv;
    }
}

// ---------------------------------------------------------------------------
// Edge attention score + fused block max. One warp per edge.
// s[e] = b2 + sum_t W2[t] * relu(u[dst][t] + v[src][t] + dist . Wd[:,t] + b1[t])
// ---------------------------------------------------------------------------
__global__ void edge_k(const int* __restrict__ src, const int* __restrict__ dst,
                       const float* __restrict__ pos,
                       const float* __restrict__ Wd, const float* __restrict__ b1,
                       const float* __restrict__ W2, const float* __restrict__ b2,
                       int E) {
    int gw = (blockIdx.x * blockDim.x + threadIdx.x) >> 5;
    int lane = threadIdx.x & 31;
    int wid = threadIdx.x >> 5;

    float score = -FLT_MAX;
    if (gw < E) {
        int sn = src[gw], dn = dst[gw];
        float dx = pos[dn * 3 + 0] - pos[sn * 3 + 0];
        float dy = pos[dn * 3 + 1] - pos[sn * 3 + 1];
        float dz = pos[dn * 3 + 2] - pos[sn * 3 + 2];

        float4 a  = ((const float4*)(g_u + (size_t)dn * 128))[lane];
        float4 bj = ((const float4*)(g_v + (size_t)sn * 128))[lane];
        float4 c0 = ((const float4*)Wd)[lane];
        float4 c1 = ((const float4*)(Wd + 128))[lane];
        float4 c2 = ((const float4*)(Wd + 256))[lane];
        float4 bb = ((const float4*)b1)[lane];
        float4 w2 = ((const float4*)W2)[lane];

        float v0 = fmaxf(a.x + bj.x + bb.x + dx * c0.x + dy * c1.x + dz * c2.x, 0.f);
        float v1 = fmaxf(a.y + bj.y + bb.y + dx * c0.y + dy * c1.y + dz * c2.y, 0.f);
        float v2 = fmaxf(a.z + bj.z + bb.z + dx * c0.z + dy * c1.z + dz * c2.z, 0.f);
        float v3 = fmaxf(a.w + bj.w + bb.w + dx * c0.w + dy * c1.w + dz * c2.w, 0.f);
        float p = v0 * w2.x + v1 * w2.y + v2 * w2.z + v3 * w2.w;

        for (int o = 16; o; o >>= 1) p += __shfl_xor_sync(0xffffffffu, p, o);
        score = p + b2[0];
        if (lane == 0) g_s[gw] = score;
    }

    __shared__ float wm[8];
    if (lane == 0) wm[wid] = score;
    __syncthreads();
    if (threadIdx.x == 0) {
        float m = wm[0];
        for (int i = 1; i < 8; i++) m = fmaxf(m, wm[i]);
        atomicMax(&g_maxkey, fkey(m));
    }
}

// ---------------------------------------------------------------------------
// Fused exp + global-sum + scatter-add. One warp per edge.
// p = exp(s - max);  aggr[dst] += h[src] * p  (UNNORMALIZED; 1/sum applied in
// the update GEMM epilogue);  g_sum += p.
// Uses red.global.add.v4.f32 (sm_90+) to quarter the REDG op count.
// ---------------------------------------------------------------------------
__global__ void scatter_k(const int* __restrict__ src, const int* __restrict__ dst, int E) {
    int gw = (blockIdx.x * blockDim.x + threadIdx.x) >> 5;
    int lane = threadIdx.x & 31;
    int wid = threadIdx.x >> 5;

    float mx = fdecode(g_maxkey);
    float p = 0.f;
    if (gw < E) {
        p = expf(g_s[gw] - mx);
        int sn = src[gw], dn = dst[gw];
        float4 x = ((const float4*)(g_h + (size_t)sn * 128))[lane];
        float* basep = g_aggr + (size_t)dn * 128 + lane * 4;
        asm volatile("red.global.add.v4.f32 [%0], {%1, %2, %3, %4};"
                     :: "l"(basep), "f"(x.x * p), "f"(x.y * p), "f"(x.z * p), "f"(x.w * p)
                     : "memory");
    }

    __shared__ float ws[8];
    if (lane == 0) ws[wid] = p;
    __syncthreads();
    if (threadIdx.x == 0) {
        float tot = ws[0];
        for (int i = 1; i < 8; i++) tot += ws[i];
        atomicAdd(&g_sum, tot);
    }
}

// ---------------------------------------------------------------------------
// Head: out[row] = relu(R[row] @ W1 + b1) @ W2 + b2 (scalar). One warp/row.
// ---------------------------------------------------------------------------
__global__ void head_k(const float* __restrict__ R, const float* __restrict__ W1,
                       const float* __restrict__ b1, const float* __restrict__ W2,
                       const float* __restrict__ b2, float* __restrict__ out, int n) {
    __shared__ float W1s[128 * 64];
    __shared__ float b1s[64];
    __shared__ float W2s[64];
    __shared__ float rows[8][128];
    int t = threadIdx.x, lane = t & 31, wid = t >> 5;
    for (int i = t; i < 128 * 64; i += 256) W1s[i] = W1[i];
    if (t < 64) { b1s[t] = b1[t]; W2s[t] = W2[t]; }
    __syncthreads();
    float b2v = b2[0];
    for (int row = blockIdx.x * 8 + wid; row < n; row += gridDim.x * 8) {
        ((float4*)rows[wid])[lane] = ((const float4*)(R + (size_t)row * 128))[lane];
        __syncwarp();
        float h0 = b1s[lane], h1 = b1s[lane + 32];
#pragma unroll 8
        for (int k = 0; k < 128; k++) {
            float x = rows[wid][k];
            h0 += x * W1s[k * 64 + lane];
            h1 += x * W1s[k * 64 + lane + 32];
        }
        float p = fmaxf(h0, 0.f) * W2s[lane] + fmaxf(h1, 0.f) * W2s[lane + 32];
        for (int o = 16; o; o >>= 1) p += __shfl_xor_sync(0xffffffffu, p, o);
        if (lane == 0) out[row] = p + b2v;
        __syncwarp();
    }
}

// ---------------------------------------------------------------------------
extern "C" void kernel_launch(void* const* d_in, const int* in_sizes, int n_in,
                              void* d_out, int out_size) {
    const float* mol_x  = (const float*)d_in[0];
    const float* pos    = (const float*)d_in[1];
    const float* rx     = (const float*)d_in[2];
    const float* tx     = (const float*)d_in[3];
    const int*   ei     = (const int*)d_in[4];
    const float* W_node = (const float*)d_in[5];
    const float* b_node = (const float*)d_in[6];
    const float* W_att1 = (const float*)d_in[7];
    const float* b_att1 = (const float*)d_in[8];
    const float* W_att2 = (const float*)d_in[9];
    const float* b_att2 = (const float*)d_in[10];
    const float* W_upd  = (const float*)d_in[11];
    const float* b_upd  = (const float*)d_in[12];
    const float* Wy1 = (const float*)d_in[13];
    const float* by1 = (const float*)d_in[14];
    const float* Wy2 = (const float*)d_in[15];
    const float* by2 = (const float*)d_in[16];
    const float* Wa1 = (const float*)d_in[17];
    const float* ba1 = (const float*)d_in[18];
    const float* Wa2 = (const float*)d_in[19];
    const float* ba2 = (const float*)d_in[20];

    int N  = in_sizes[0] / 64;
    int NR = in_sizes[2] / 64;
    int NT = in_sizes[3] / 64;
    int E  = in_sizes[4] / 2;
    const int* srcP = ei;
    const int* dstP = ei + E;

    float* out   = (float*)d_out;
    float* out_y = out;             // pred_yield  [NR]
    float* out_a = out + NR;        // pred_activity [NT]
    float* out_m = out + NR + NT;   // mol_feats [N,128]

    float *hP, *uP, *vP, *rhP, *thP, *agP, *sumP;
    cudaGetSymbolAddress((void**)&hP,  g_h);
    cudaGetSymbolAddress((void**)&uP,  g_u);
    cudaGetSymbolAddress((void**)&vP,  g_v);
    cudaGetSymbolAddress((void**)&rhP, g_rh);
    cudaGetSymbolAddress((void**)&thP, g_th);
    cudaGetSymbolAddress((void**)&agP, g_aggr);
    cudaGetSymbolAddress((void**)&sumP, g_sum);

    int smem64  = (64 * 128 + 32 * 64) * 4;   // 40 KB
    int smem128 = (128 * 128 + 32 * 128) * 4; // 80 KB
    cudaFuncSetAttribute(gemm_k, cudaFuncAttributeMaxDynamicSharedMemorySize, smem128);

    // Persistent grids: amortize the Ws smem prologue over the row loop,
    // keep every block resident in one wave.
    auto pgrid = [](int rows, int cap) {
        int tiles = (rows + 31) / 32;
        return tiles < cap ? tiles : cap;
    };
    const int CAP64  = 4 * 148;  // 40 KB smem -> 5 blocks/SM fit; 4/SM is one wave
    const int CAP128 = 2 * 148;  // 80 KB smem -> 2 blocks/SM

    init_k<<<512, 256>>>(agP, N * 128);

    // node encoders
    gemm_k<<<pgrid(N,  CAP64), 128, smem64>>>(mol_x, W_node, b_node, hP,  N,  64, nullptr);
    gemm_k<<<pgrid(NR, CAP64), 128, smem64>>>(rx,    W_node, b_node, rhP, NR, 64, nullptr);
    gemm_k<<<pgrid(NT, CAP64), 128, smem64>>>(tx,    W_node, b_node, thP, NT, 64, nullptr);

    // per-node attention projections: u = h@W_att1[0:128], v = h@W_att1[128:256]
    gemm_k<<<pgrid(N, CAP128), 128, smem128>>>(hP, W_att1,             nullptr, uP, N, 128, nullptr);
    gemm_k<<<pgrid(N, CAP128), 128, smem128>>>(hP, W_att1 + 128 * 128, nullptr, vP, N, 128, nullptr);

    // per-edge score + fused global max
    edge_k<<<(E + 7) / 8, 256>>>(srcP, dstP, pos, W_att1 + 256 * 128, b_att1, W_att2, b_att2, E);

    // fused exp + sum + unnormalized scatter-add
    scatter_k<<<(E + 7) / 8, 256>>>(srcP, dstP, E);

    // update GEMM -> mol_feats, with 1/sum folded into the epilogue
    gemm_k<<<pgrid(N, CAP128), 128, smem128>>>(agP, W_upd, b_upd, out_m, N, 128, sumP);

    // heads
    head_k<<<(NR + 7) / 8, 256>>>(rhP, Wy1, by1, Wy2, by2, out_y, NR);
    head_k<<<(NT + 7) / 8, 256>>>(thP, Wa1, ba1, Wa2, ba2, out_a, NT);
}